// round 8
// baseline (speedup 1.0000x reference)
#include <cuda_runtime.h>
#include <cstdint>

// ---------------------------------------------------------------------------
// EncoderBlock: pre-norm transformer block.
// GEMMs via mma.sync m16n8k8 tf32 + ldmatrix; fused QKV; fused flash attention
// (Q-tile 64, 2 CTAs/SM, register-resident softmax stats).
// B=2, S=2048, D=1024, H=16, DK=64, DFF=4096
// ---------------------------------------------------------------------------

namespace {
constexpr int B_ = 2, S_ = 2048, D_ = 1024, H_ = 16, DK_ = 64, DFF_ = 4096;
constexpr int ROWS_ = B_ * S_;            // 4096
constexpr int QKV_LD = 3 * D_;            // 3072
constexpr float EPS_ = 1e-6f;
}

// Scratch (allocation-free: __device__ globals)
__device__ __align__(16) float g_ln[ROWS_ * D_];
__device__ __align__(16) float g_qkv[ROWS_ * QKV_LD];
__device__ __align__(16) float g_vT[B_ * H_ * DK_ * S_];
__device__ __align__(16) float g_attn[ROWS_ * D_];
__device__ __align__(16) float g_x2[ROWS_ * D_];
__device__ __align__(16) float g_hbuf[ROWS_ * DFF_];
__device__ __align__(16) float g_wr[12 * 1024 * 1024];   // rounded weights (48MB)
__device__ __align__(16) float g_bqkv[QKV_LD];

// ---------------------------------------------------------------------------
// PTX helpers
// ---------------------------------------------------------------------------
__device__ __forceinline__ uint32_t smem_u32(const void* p) {
    uint32_t a;
    asm("{ .reg .u64 t; cvta.to.shared.u64 t, %1; cvt.u32.u64 %0, t; }"
        : "=r"(a) : "l"(p));
    return a;
}

__device__ __forceinline__ void cp_async16(uint32_t s, const void* g) {
    asm volatile("cp.async.cg.shared.global [%0], [%1], 16;" :: "r"(s), "l"(g));
}
#define CP_COMMIT() asm volatile("cp.async.commit_group;" ::: "memory")
#define CP_WAIT(n)  asm volatile("cp.async.wait_group %0;" :: "n"(n) : "memory")

__device__ __forceinline__ uint32_t f2tf32(float f) {
    uint32_t u;
    asm("cvt.rna.tf32.f32 %0, %1;" : "=r"(u) : "f"(f));
    return u;
}
__device__ __forceinline__ float rndtf(float f) { return __uint_as_float(f2tf32(f)); }

__device__ __forceinline__ void mma_tf32(float* c, const uint32_t* a, const uint32_t* b) {
    asm volatile(
        "mma.sync.aligned.m16n8k8.row.col.f32.tf32.tf32.f32 "
        "{%0,%1,%2,%3}, {%4,%5,%6,%7}, {%8,%9}, {%0,%1,%2,%3};"
        : "+f"(c[0]), "+f"(c[1]), "+f"(c[2]), "+f"(c[3])
        : "r"(a[0]), "r"(a[1]), "r"(a[2]), "r"(a[3]), "r"(b[0]), "r"(b[1]));
}

__device__ __forceinline__ void ldsm_x4(uint32_t* r, uint32_t saddr) {
    asm volatile("ldmatrix.sync.aligned.m8n8.x4.shared.b16 {%0,%1,%2,%3}, [%4];"
                 : "=r"(r[0]), "=r"(r[1]), "=r"(r[2]), "=r"(r[3]) : "r"(saddr));
}

// ---------------------------------------------------------------------------
// Fused weight pre-rounding. dst: [wq 1M][wk 1M][wv 1M][wo 1M][w1 4M][w2 4M]
// ---------------------------------------------------------------------------
__global__ void round_all_kernel(const float* __restrict__ wq, const float* __restrict__ wk,
                                 const float* __restrict__ wv, const float* __restrict__ wo,
                                 const float* __restrict__ w1, const float* __restrict__ w2,
                                 float* __restrict__ dst) {
    constexpr int M1 = 1024 * 1024;
    const int y = blockIdx.y;
    if (y < 4 && blockIdx.x >= 1024) return;
    const float* src;
    size_t off;
    switch (y) {
        case 0: src = wq; off = 0; break;
        case 1: src = wk; off = (size_t)M1; break;
        case 2: src = wv; off = 2 * (size_t)M1; break;
        case 3: src = wo; off = 3 * (size_t)M1; break;
        case 4: src = w1; off = 4 * (size_t)M1; break;
        default: src = w2; off = 8 * (size_t)M1; break;
    }
    const int i = blockIdx.x * 256 + threadIdx.x;
    float4 v = reinterpret_cast<const float4*>(src)[i];
    v.x = rndtf(v.x); v.y = rndtf(v.y); v.z = rndtf(v.z); v.w = rndtf(v.w);
    reinterpret_cast<float4*>(dst + off)[i] = v;
}

__global__ void concat_bias_kernel(const float* __restrict__ bq, const float* __restrict__ bk,
                                   const float* __restrict__ bv, float* __restrict__ dst) {
    const int i = blockIdx.x * 256 + threadIdx.x;
    if (i < 1024) dst[i] = bq[i];
    else if (i < 2048) dst[i] = bk[i - 1024];
    else dst[i] = bv[i - 2048];
}

// ---------------------------------------------------------------------------
// LayerNorm (exact fp32): unbiased std (ddof=1), scalar alpha/beta.
// ---------------------------------------------------------------------------
__global__ void layernorm_kernel(const float* __restrict__ x, float* __restrict__ y,
                                 const float* __restrict__ alpha,
                                 const float* __restrict__ beta) {
    __shared__ float red_s[256];
    __shared__ float red_q[256];
    const int tid = threadIdx.x;
    const size_t off = (size_t)blockIdx.x * D_;
    float4 r = reinterpret_cast<const float4*>(x + off)[tid];
    float s = r.x + r.y + r.z + r.w;
    float q = r.x * r.x + r.y * r.y + r.z * r.z + r.w * r.w;
    red_s[tid] = s;
    red_q[tid] = q;
    __syncthreads();
    #pragma unroll
    for (int st = 128; st > 0; st >>= 1) {
        if (tid < st) { red_s[tid] += red_s[tid + st]; red_q[tid] += red_q[tid + st]; }
        __syncthreads();
    }
    const float mean = red_s[0] * (1.0f / D_);
    float var = (red_q[0] - (float)D_ * mean * mean) * (1.0f / (float)(D_ - 1));
    var = fmaxf(var, 0.0f);
    const float sc = alpha[0] / (sqrtf(var) + EPS_);
    const float sh = beta[0];
    float4 o;
    o.x = rndtf((r.x - mean) * sc + sh);
    o.y = rndtf((r.y - mean) * sc + sh);
    o.z = rndtf((r.z - mean) * sc + sh);
    o.w = rndtf((r.w - mean) * sc + sh);
    reinterpret_cast<float4*>(y + off)[tid] = o;
}

// ---------------------------------------------------------------------------
// V transpose: vT[(b*H+h)][n][s] = qkv[b][s][2048 + h*DK + n]
// ---------------------------------------------------------------------------
__global__ void transpose_v_kernel(const float* __restrict__ v, float* __restrict__ vT) {
    __shared__ float t[32][33];
    const int bh = blockIdx.z;
    const int b = bh / H_, h = bh % H_;
    const int s0 = blockIdx.x * 32, n0 = blockIdx.y * 32;
    const int tx = threadIdx.x, ty = threadIdx.y;   // 32 x 8
    const float* src = v + ((long long)b * S_ + s0) * QKV_LD + h * DK_ + n0;
    #pragma unroll
    for (int i = 0; i < 32; i += 8)
        t[ty + i][tx] = src[(long long)(ty + i) * QKV_LD + tx];
    __syncthreads();
    float* dst = vT + ((long long)bh * DK_ + n0) * S_ + s0;
    #pragma unroll
    for (int i = 0; i < 32; i += 8)
        dst[(long long)(ty + i) * S_ + tx] = t[tx][ty + i];
}

// ---------------------------------------------------------------------------
// tf32 tensor-core GEMM (NT). Proven 128x128x32 tile, 2 CTAs/SM.
// ---------------------------------------------------------------------------
template <bool RELU, bool ROUNDOUT>
__global__ void __launch_bounds__(256, 2)
mma_gemm(const float* __restrict__ A, const float* __restrict__ Bm,
         const float* __restrict__ bias, const float* __restrict__ res,
         float* __restrict__ C,
         int K, int lda, int ldb, int ldc, float scale) {
    constexpr int STGF = 256 * 32;
    constexpr int BOFF = 128 * 32;

    extern __shared__ float sm[];

    const int tid = threadIdx.x;
    const int wid = tid >> 5;
    const int lane = tid & 31;
    const int grp = lane >> 2;
    const int tid4 = lane & 3;
    const int wm0 = (wid >> 2) * 64;
    const int wn0 = (wid & 3) * 32;

    const int l7 = lane & 7;
    const int aRB = ((lane >> 3) & 1) * 8 + l7;
    const int aCB = lane >> 4;
    const int bRB = ((lane >> 4) & 1) * 8 + l7;
    const int bCB = (lane >> 3) & 1;

    const int row0 = blockIdx.y * 128;
    const int col0 = blockIdx.x * 128;

    int aGo[4]; uint32_t aSm[4];
    #pragma unroll
    for (int l = 0; l < 4; l++) {
        const int idx4 = tid + l * 256;
        const int r = idx4 >> 3, ch = idx4 & 7;
        aGo[l] = (row0 + r) * lda + ch * 4;
        aSm[l] = (uint32_t)(r * 32 + ((ch ^ (r & 7)) << 2)) * 4u;
    }
    int bGo[4]; uint32_t bSm[4];
    #pragma unroll
    for (int l = 0; l < 4; l++) {
        const int idx4 = tid + l * 256;
        const int r = idx4 >> 3, ch = idx4 & 7;
        bGo[l] = (col0 + r) * ldb + ch * 4;
        bSm[l] = (uint32_t)(BOFF + r * 32 + ((ch ^ (r & 7)) << 2)) * 4u;
    }
    const uint32_t smBase = smem_u32(sm);

    float acc[4][4][4];
    #pragma unroll
    for (int i = 0; i < 4; i++)
        #pragma unroll
        for (int j = 0; j < 4; j++)
            #pragma unroll
            for (int e = 0; e < 4; e++) acc[i][j][e] = 0.0f;

    const int nch = K / 32;

    #pragma unroll
    for (int s = 0; s < 2; s++) {
        const uint32_t sb = smBase + (uint32_t)(s % 3) * STGF * 4u;
        const int k0 = s * 32;
        #pragma unroll
        for (int l = 0; l < 4; l++) cp_async16(sb + aSm[l], A + aGo[l] + k0);
        #pragma unroll
        for (int l = 0; l < 4; l++) cp_async16(sb + bSm[l], Bm + bGo[l] + k0);
        CP_COMMIT();
    }

    for (int ci = 0; ci < nch; ci++) {
        if (ci + 2 < nch) { CP_WAIT(1); } else { CP_WAIT(0); }
        __syncthreads();
        if (ci + 2 < nch) {
            const int s = ci + 2;
            const uint32_t sb = smBase + (uint32_t)(s % 3) * STGF * 4u;
            const int k0 = s * 32;
            #pragma unroll
            for (int l = 0; l < 4; l++) cp_async16(sb + aSm[l], A + aGo[l] + k0);
            #pragma unroll
            for (int l = 0; l < 4; l++) cp_async16(sb + bSm[l], Bm + bGo[l] + k0);
            CP_COMMIT();
        }

        const uint32_t suA = smBase + (uint32_t)(ci % 3) * STGF * 4u;
        const uint32_t suB = suA + (uint32_t)BOFF * 4u;

        #pragma unroll
        for (int ks = 0; ks < 4; ks++) {
            const uint32_t aSw = (uint32_t)(((2 * ks + aCB) ^ l7) << 4);
            const uint32_t bSw = (uint32_t)(((2 * ks + bCB) ^ l7) << 4);
            uint32_t a[4][4];
            #pragma unroll
            for (int ma = 0; ma < 4; ma++)
                ldsm_x4(a[ma], suA + (uint32_t)(wm0 + ma * 16 + aRB) * 128u + aSw);
            uint32_t bq[2][4];
            #pragma unroll
            for (int np = 0; np < 2; np++)
                ldsm_x4(bq[np], suB + (uint32_t)(wn0 + np * 16 + bRB) * 128u + bSw);
            #pragma unroll
            for (int ma = 0; ma < 4; ma++)
                #pragma unroll
                for (int na = 0; na < 4; na++)
                    mma_tf32(acc[ma][na], a[ma], &bq[na >> 1][(na & 1) * 2]);
        }
    }

    #pragma unroll
    for (int ma = 0; ma < 4; ma++) {
        const int rr = row0 + wm0 + ma * 16 + grp;
        #pragma unroll
        for (int na = 0; na < 4; na++) {
            const int cc = col0 + wn0 + na * 8 + tid4 * 2;
            float2 v0, v1;
            v0.x = acc[ma][na][0] * scale; v0.y = acc[ma][na][1] * scale;
            v1.x = acc[ma][na][2] * scale; v1.y = acc[ma][na][3] * scale;
            if (bias) {
                const float2 bv = *reinterpret_cast<const float2*>(bias + cc);
                v0.x += bv.x; v0.y += bv.y; v1.x += bv.x; v1.y += bv.y;
            }
            if (RELU) {
                v0.x = fmaxf(v0.x, 0.0f); v0.y = fmaxf(v0.y, 0.0f);
                v1.x = fmaxf(v1.x, 0.0f); v1.y = fmaxf(v1.y, 0.0f);
            }
            if (ROUNDOUT) {
                v0.x = rndtf(v0.x); v0.y = rndtf(v0.y);
                v1.x = rndtf(v1.x); v1.y = rndtf(v1.y);
            }
            const long long o0 = (long long)rr * ldc + cc;
            const long long o1 = (long long)(rr + 8) * ldc + cc;
            if (res) {
                const float2 r0 = *reinterpret_cast<const float2*>(res + o0);
                const float2 r1 = *reinterpret_cast<const float2*>(res + o1);
                v0.x += r0.x; v0.y += r0.y; v1.x += r1.x; v1.y += r1.y;
            }
            *reinterpret_cast<float2*>(C + o0) = v0;
            *reinterpret_cast<float2*>(C + o1) = v1;
        }
    }
}

// ---------------------------------------------------------------------------
// Fused flash attention, 2 CTAs/SM version.
// Per block: 64 q-rows, 128-kv tiles, 16 iterations.
// Warp layout (both phases): 4(M) x 2(N); each warp owns rows 16*(wid>>1).
// m/l/corr live in registers. Single-buffered K/VT; reloads overlap compute.
// SMEM (floats): Q[64x64]=4096, K[128x64]=8192, VT[64x128]=8192,
//                P[64x128]=8192, red[64x2]=128.  Total 28800 fl = 112.5KB.
// ---------------------------------------------------------------------------
namespace fa {
constexpr int oQ = 0, oK = 4096, oVT = 12288, oP = 20480, oRed = 28672;
constexpr int FTOT = 28800;
constexpr int SMEM_BYTES = FTOT * 4;           // 115200
constexpr int NIT = S_ / 128;                  // 16
}

__global__ void __launch_bounds__(256, 2)
flash_attn_kernel(const float* __restrict__ q, const float* __restrict__ k,
                  const float* __restrict__ vT, const int* __restrict__ mask,
                  float* __restrict__ attn) {
    using namespace fa;
    extern __shared__ float sm[];
    const uint32_t smb = smem_u32(sm);

    const int tid = threadIdx.x, wid = tid >> 5, lane = tid & 31;
    const int grp = lane >> 2, tid4 = lane & 3;
    const int wmS = (wid >> 1) * 16;    // rows owned (S and PV phases)
    const int cw = wid & 1;             // column-warp index
    const int wnS = cw * 64;            // S cols
    const int wnB = cw * 32;            // PV dk cols

    const int l7 = lane & 7;
    const int aRB = ((lane >> 3) & 1) * 8 + l7;
    const int aCB = lane >> 4;
    const int bRB = ((lane >> 4) & 1) * 8 + l7;
    const int bCB = (lane >> 3) & 1;

    const int qt = blockIdx.x;          // 0..31 (64-row q tiles)
    const int bh = blockIdx.y;
    const int b = bh >> 4, hh = bh & 15;
    const int q0 = qt * 64;
    const float* Qg = q + ((size_t)(b * S_ + q0)) * QKV_LD + hh * 64;
    const float* Kg = k + ((size_t)(b * S_)) * QKV_LD + hh * 64;
    const float* Vg = vT + (size_t)bh * 64 * S_;
    const int* maskb = mask + b * S_;

    // prologue: group0 = {Q, K0}, group1 = {VT0}
    #pragma unroll
    for (int l = 0; l < 4; l++) {
        const int i4 = tid + l * 256;
        const int r = i4 >> 4, c = i4 & 15;
        cp_async16(smb + (uint32_t)(oQ + r * 64 + ((c ^ (r & 7)) << 2)) * 4u,
                   Qg + (size_t)r * QKV_LD + c * 4);
    }
    #pragma unroll
    for (int l = 0; l < 8; l++) {
        const int i4 = tid + l * 256;
        const int r = i4 >> 4, c = i4 & 15;
        cp_async16(smb + (uint32_t)(oK + r * 64 + ((c ^ (r & 7)) << 2)) * 4u,
                   Kg + (size_t)r * QKV_LD + c * 4);
    }
    CP_COMMIT();
    #pragma unroll
    for (int l = 0; l < 8; l++) {
        const int i4 = tid + l * 256;
        const int r = i4 >> 5, c = i4 & 31;
        cp_async16(smb + (uint32_t)(oVT + r * 128 + ((c ^ (r & 7)) << 2)) * 4u,
                   Vg + (size_t)r * S_ + c * 4);
    }
    CP_COMMIT();

    float acc_o[4][4];
    #pragma unroll
    for (int j = 0; j < 4; j++)
        #pragma unroll
        for (int e = 0; e < 4; e++) acc_o[j][e] = 0.0f;

    float m0 = -3.0e38f, m1 = -3.0e38f;    // running max for rows wmS+grp, +8
    float l0 = 0.0f, l1 = 0.0f;            // running denom

    const uint32_t qBase = smb + (uint32_t)oQ * 4u;
    const uint32_t kBase = smb + (uint32_t)oK * 4u;
    const uint32_t pBase = smb + (uint32_t)oP * 4u;
    const uint32_t vBase = smb + (uint32_t)oVT * 4u;
    const int rA = wmS + grp;              // first owned row
    const int red0 = oRed + rA * 2;
    const int red1 = oRed + (rA + 8) * 2;

    for (int it = 0; it < NIT; ++it) {
        const int kv0 = it * 128;
        CP_WAIT(1);                 // K(it) (and Q on it==0) ready
        __syncthreads();

        // ---- S = Q K^T (M=64, N=128, K=64); warp: 16 rows x 64 cols ----
        float acc_s[8][4];
        #pragma unroll
        for (int j = 0; j < 8; j++)
            #pragma unroll
            for (int e = 0; e < 4; e++) acc_s[j][e] = 0.0f;

        #pragma unroll
        for (int ks = 0; ks < 8; ks++) {
            const uint32_t aSw = (uint32_t)(((2 * ks + aCB) ^ l7) << 4);
            const uint32_t bSw = (uint32_t)(((2 * ks + bCB) ^ l7) << 4);
            uint32_t a[4];
            ldsm_x4(a, qBase + (uint32_t)(wmS + aRB) * 256u + aSw);
            uint32_t bq[4][4];
            #pragma unroll
            for (int np = 0; np < 4; np++)
                ldsm_x4(bq[np], kBase + (uint32_t)(wnS + np * 16 + bRB) * 256u + bSw);
            #pragma unroll
            for (int na = 0; na < 8; na++)
                mma_tf32(acc_s[na], a, &bq[na >> 1][(na & 1) * 2]);
        }
        __syncthreads();            // all K reads complete

        if (it + 1 < NIT) {         // reload K (overlaps softmax+PV)
            const float* Kn = Kg + (size_t)(kv0 + 128) * QKV_LD;
            #pragma unroll
            for (int l = 0; l < 8; l++) {
                const int i4 = tid + l * 256;
                const int r = i4 >> 4, c = i4 & 15;
                cp_async16(smb + (uint32_t)(oK + r * 64 + ((c ^ (r & 7)) << 2)) * 4u,
                           Kn + (size_t)r * QKV_LD + c * 4);
            }
            CP_COMMIT();
        }

        // ---- mask + scale + row max ----
        float p0 = -3.0e38f, p1 = -3.0e38f;
        #pragma unroll
        for (int na = 0; na < 8; na++) {
            const int cg = kv0 + wnS + na * 8 + tid4 * 2;
            const int2 mm = *reinterpret_cast<const int2*>(maskb + cg);
            float* s = acc_s[na];
            s[0] = mm.x ? s[0] * 0.125f : -1e9f;
            s[1] = mm.y ? s[1] * 0.125f : -1e9f;
            s[2] = mm.x ? s[2] * 0.125f : -1e9f;
            s[3] = mm.y ? s[3] * 0.125f : -1e9f;
            p0 = fmaxf(p0, fmaxf(s[0], s[1]));
            p1 = fmaxf(p1, fmaxf(s[2], s[3]));
        }
        #pragma unroll
        for (int d2 = 1; d2 < 4; d2 <<= 1) {
            p0 = fmaxf(p0, __shfl_xor_sync(0xffffffffu, p0, d2));
            p1 = fmaxf(p1, __shfl_xor_sync(0xffffffffu, p1, d2));
        }
        if (tid4 == 0) { sm[red0 + cw] = p0; sm[red1 + cw] = p1; }
        __syncthreads();
        const float mn0 = fmaxf(m0, fmaxf(sm[red0], sm[red0 + 1]));
        const float mn1 = fmaxf(m1, fmaxf(sm[red1], sm[red1 + 1]));
        const float c0 = __expf(m0 - mn0);
        const float c1 = __expf(m1 - mn1);
        m0 = mn0; m1 = mn1;
        __syncthreads();            // red reuse guard (max read -> sum write)

        // ---- exp, P write (rounded), row sum ----
        float s0sum = 0.0f, s1sum = 0.0f;
        #pragma unroll
        for (int na = 0; na < 8; na++) {
            float* s = acc_s[na];
            s[0] = __expf(s[0] - mn0);
            s[1] = __expf(s[1] - mn0);
            s[2] = __expf(s[2] - mn1);
            s[3] = __expf(s[3] - mn1);
            s0sum += s[0] + s[1];
            s1sum += s[2] + s[3];
            const int ch = cw * 16 + na * 2 + (tid4 >> 1);
            const int fo = oP + rA * 128 + ((ch ^ grp) << 2) + ((tid4 & 1) << 1);
            float2 q0v, q1v;
            q0v.x = rndtf(s[0]); q0v.y = rndtf(s[1]);
            q1v.x = rndtf(s[2]); q1v.y = rndtf(s[3]);
            *reinterpret_cast<float2*>(&sm[fo]) = q0v;
            *reinterpret_cast<float2*>(&sm[fo + 1024]) = q1v;
        }
        #pragma unroll
        for (int d2 = 1; d2 < 4; d2 <<= 1) {
            s0sum += __shfl_xor_sync(0xffffffffu, s0sum, d2);
            s1sum += __shfl_xor_sync(0xffffffffu, s1sum, d2);
        }
        if (tid4 == 0) { sm[red0 + cw] = s0sum; sm[red1 + cw] = s1sum; }

        if (it + 1 < NIT) { CP_WAIT(1); } else { CP_WAIT(0); }   // VT(it) ready
        __syncthreads();            // P + psum + VT visible

        l0 = l0 * c0 + (sm[red0] + sm[red0 + 1]);
        l1 = l1 * c1 + (sm[red1] + sm[red1 + 1]);
        #pragma unroll
        for (int na = 0; na < 4; na++) {
            acc_o[na][0] *= c0; acc_o[na][1] *= c0;
            acc_o[na][2] *= c1; acc_o[na][3] *= c1;
        }

        // ---- PV: O += P @ VT^T (M=64, N=64, K=128); warp: 16 rows x 32 cols ----
        #pragma unroll
        for (int ks = 0; ks < 16; ks++) {
            const uint32_t aSw = (uint32_t)(((2 * ks + aCB) ^ l7) << 4);
            const uint32_t bSw = (uint32_t)(((2 * ks + bCB) ^ l7) << 4);
            uint32_t a[4];
            ldsm_x4(a, pBase + (uint32_t)(wmS + aRB) * 512u + aSw);
            uint32_t bq[2][4];
            #pragma unroll
            for (int np = 0; np < 2; np++)
                ldsm_x4(bq[np], vBase + (uint32_t)(wnB + np * 16 + bRB) * 512u + bSw);
            #pragma unroll
            for (int na = 0; na < 4; na++)
                mma_tf32(acc_o[na], a, &bq[na >> 1][(na & 1) * 2]);
        }
        __syncthreads();            // VT + P reads complete

        if (it + 1 < NIT) {         // reload VT (overlaps next S-MMA)
            const float* Vn = Vg + kv0 + 128;
            #pragma unroll
            for (int l = 0; l < 8; l++) {
                const int i4 = tid + l * 256;
                const int r = i4 >> 5, c = i4 & 31;
                cp_async16(smb + (uint32_t)(oVT + r * 128 + ((c ^ (r & 7)) << 2)) * 4u,
                           Vn + (size_t)r * S_ + c * 4);
            }
            CP_COMMIT();
        }
    }

    // ---- normalize and store (tf32-rounded; feeds Wo GEMM) ----
    const float inv0 = 1.0f / l0;
    const float inv1 = 1.0f / l1;
    #pragma unroll
    for (int na = 0; na < 4; na++) {
        const int cd = wnB + na * 8 + tid4 * 2;
        float2 v0, v1;
        v0.x = rndtf(acc_o[na][0] * inv0);
        v0.y = rndtf(acc_o[na][1] * inv0);
        v1.x = rndtf(acc_o[na][2] * inv1);
        v1.y = rndtf(acc_o[na][3] * inv1);
        const size_t o0 = ((size_t)(b * S_ + q0 + rA)) * D_ + hh * 64 + cd;
        const size_t o1 = o0 + (size_t)8 * D_;
        *reinterpret_cast<float2*>(attn + o0) = v0;
        *reinterpret_cast<float2*>(attn + o1) = v1;
    }
}

// ---------------------------------------------------------------------------
// kernel_launch
// ---------------------------------------------------------------------------
extern "C" void kernel_launch(void* const* d_in, const int* in_sizes, int n_in,
                              void* d_out, int out_size) {
    const float* x    = (const float*)d_in[0];
    const int*   msk  = (const int*)  d_in[1];
    const float* wq   = (const float*)d_in[2];
    const float* bq   = (const float*)d_in[3];
    const float* wk   = (const float*)d_in[4];
    const float* bk_  = (const float*)d_in[5];
    const float* wv   = (const float*)d_in[6];
    const float* bv   = (const float*)d_in[7];
    const float* wo   = (const float*)d_in[8];
    const float* bo   = (const float*)d_in[9];
    const float* w1   = (const float*)d_in[10];
    const float* b1   = (const float*)d_in[11];
    const float* w2   = (const float*)d_in[12];
    const float* b2   = (const float*)d_in[13];
    const float* a1   = (const float*)d_in[14];
    const float* be1  = (const float*)d_in[15];
    const float* a2   = (const float*)d_in[16];
    const float* be2  = (const float*)d_in[17];
    float* out = (float*)d_out;

    float *ln, *qkv, *vT, *attn, *x2, *hb, *wr, *bqkv;
    cudaGetSymbolAddress((void**)&ln,   g_ln);
    cudaGetSymbolAddress((void**)&qkv,  g_qkv);
    cudaGetSymbolAddress((void**)&vT,   g_vT);
    cudaGetSymbolAddress((void**)&attn, g_attn);
    cudaGetSymbolAddress((void**)&x2,   g_x2);
    cudaGetSymbolAddress((void**)&hb,   g_hbuf);
    cudaGetSymbolAddress((void**)&wr,   g_wr);
    cudaGetSymbolAddress((void**)&bqkv, g_bqkv);

    constexpr int M1 = 1024 * 1024;
    float* wqkvr = wr;            // [3072, 1024] (wq|wk|wv)
    float* wor = wr + 3 * M1;
    float* w1r = wr + 4 * M1;
    float* w2r = wr + 8 * M1;

    constexpr int SMG = 3 * 256 * 32 * 4;   // 98304 (128x128)
    cudaFuncSetAttribute(mma_gemm<false, false>, cudaFuncAttributeMaxDynamicSharedMemorySize, SMG);
    cudaFuncSetAttribute(mma_gemm<false, true>,  cudaFuncAttributeMaxDynamicSharedMemorySize, SMG);
    cudaFuncSetAttribute(mma_gemm<true,  true>,  cudaFuncAttributeMaxDynamicSharedMemorySize, SMG);
    cudaFuncSetAttribute(flash_attn_kernel, cudaFuncAttributeMaxDynamicSharedMemorySize,
                         fa::SMEM_BYTES);

    // 0. weight rounding + bias concat
    round_all_kernel<<<dim3(4096, 6), 256>>>(wq, wk, wv, wo, w1, w2, wr);
    concat_bias_kernel<<<12, 256>>>(bq, bk_, bv, bqkv);

    // 1. LN1 (tf32-rounded output)
    layernorm_kernel<<<ROWS_, 256>>>(x, ln, a1, be1);

    // 2. fused QKV projection: [4096, 3072]
    mma_gemm<false, true><<<dim3(QKV_LD / 128, ROWS_ / 128), 256, SMG>>>(
        ln, wqkvr, bqkv, nullptr, qkv, D_, D_, D_, QKV_LD, 1.0f);

    // 3. vT from qkv's V columns
    transpose_v_kernel<<<dim3(S_ / 32, DK_ / 32, B_ * H_), dim3(32, 8)>>>(
        qkv + 2 * D_, vT);

    // 4. fused flash attention -> attn (rounded); 64-row q tiles
    flash_attn_kernel<<<dim3(S_ / 64, B_ * H_), 256, fa::SMEM_BYTES>>>(
        qkv, qkv + D_, vT, msk, attn);

    // 5. x2 = attn @ wo^T + bo + x
    mma_gemm<false, false><<<dim3(D_ / 128, ROWS_ / 128), 256, SMG>>>(
        attn, wor, bo, x, x2, D_, D_, D_, D_, 1.0f);

    // 6. LN2 (rounded)
    layernorm_kernel<<<ROWS_, 256>>>(x2, ln, a2, be2);

    // 7. h = relu(ln @ w1^T + b1)
    mma_gemm<true, true><<<dim3(DFF_ / 128, ROWS_ / 128), 256, SMG>>>(
        ln, w1r, b1, nullptr, hb, D_, D_, D_, DFF_, 1.0f);

    // 8. out = h @ w2^T + b2 + x2
    mma_gemm<false, false><<<dim3(D_ / 128, ROWS_ / 128), 256, SMG>>>(
        hb, w2r, b2, x2, out, DFF_, DFF_, DFF_, D_, 1.0f);
}

// round 9
// speedup vs baseline: 1.7505x; 1.7505x over previous
#include <cuda_runtime.h>
#include <cuda_fp16.h>
#include <cstdint>

// ---------------------------------------------------------------------------
// EncoderBlock: pre-norm transformer block.
// GEMMs + flash attention via mma.sync m16n8k16 fp16 (fp32 accumulate).
// All tensor-op operands stored half (same 10-bit mantissa as tf32).
// B=2, S=2048, D=1024, H=16, DK=64, DFF=4096
// ---------------------------------------------------------------------------

namespace {
constexpr int B_ = 2, S_ = 2048, D_ = 1024, H_ = 16, DK_ = 64, DFF_ = 4096;
constexpr int ROWS_ = B_ * S_;            // 4096
constexpr int QKV_LD = 3 * D_;            // 3072
constexpr float EPS_ = 1e-6f;
}

// Scratch (allocation-free: __device__ globals)
__device__ __align__(16) __half g_ln[ROWS_ * D_];
__device__ __align__(16) __half g_qkv[ROWS_ * QKV_LD];
__device__ __align__(16) __half g_vT[B_ * H_ * DK_ * S_];
__device__ __align__(16) __half g_attn[ROWS_ * D_];
__device__ __align__(16) float  g_x2[ROWS_ * D_];
__device__ __align__(16) __half g_hbuf[ROWS_ * DFF_];
__device__ __align__(16) __half g_wr[12 * 1024 * 1024];   // half weights (24MB)
__device__ __align__(16) float  g_bqkv[QKV_LD];

// ---------------------------------------------------------------------------
// PTX helpers
// ---------------------------------------------------------------------------
__device__ __forceinline__ uint32_t smem_u32(const void* p) {
    uint32_t a;
    asm("{ .reg .u64 t; cvta.to.shared.u64 t, %1; cvt.u32.u64 %0, t; }"
        : "=r"(a) : "l"(p));
    return a;
}

__device__ __forceinline__ void cp_async16(uint32_t s, const void* g) {
    asm volatile("cp.async.cg.shared.global [%0], [%1], 16;" :: "r"(s), "l"(g));
}
#define CP_COMMIT() asm volatile("cp.async.commit_group;" ::: "memory")
#define CP_WAIT(n)  asm volatile("cp.async.wait_group %0;" :: "n"(n) : "memory")

__device__ __forceinline__ void mma_f16(float* c, const uint32_t* a, const uint32_t* b) {
    asm volatile(
        "mma.sync.aligned.m16n8k16.row.col.f32.f16.f16.f32 "
        "{%0,%1,%2,%3}, {%4,%5,%6,%7}, {%8,%9}, {%0,%1,%2,%3};"
        : "+f"(c[0]), "+f"(c[1]), "+f"(c[2]), "+f"(c[3])
        : "r"(a[0]), "r"(a[1]), "r"(a[2]), "r"(a[3]), "r"(b[0]), "r"(b[1]));
}

__device__ __forceinline__ void ldsm_x4(uint32_t* r, uint32_t saddr) {
    asm volatile("ldmatrix.sync.aligned.m8n8.x4.shared.b16 {%0,%1,%2,%3}, [%4];"
                 : "=r"(r[0]), "=r"(r[1]), "=r"(r[2]), "=r"(r[3]) : "r"(saddr));
}

// ---------------------------------------------------------------------------
// Weight conversion fp32 -> fp16. dst: [wq 1M][wk 1M][wv 1M][wo 1M][w1 4M][w2 4M]
// ---------------------------------------------------------------------------
__global__ void round_all_kernel(const float* __restrict__ wq, const float* __restrict__ wk,
                                 const float* __restrict__ wv, const float* __restrict__ wo,
                                 const float* __restrict__ w1, const float* __restrict__ w2,
                                 __half* __restrict__ dst) {
    constexpr int M1 = 1024 * 1024;
    const int y = blockIdx.y;
    if (y < 4 && blockIdx.x >= 1024) return;
    const float* src;
    size_t off;
    switch (y) {
        case 0: src = wq; off = 0; break;
        case 1: src = wk; off = (size_t)M1; break;
        case 2: src = wv; off = 2 * (size_t)M1; break;
        case 3: src = wo; off = 3 * (size_t)M1; break;
        case 4: src = w1; off = 4 * (size_t)M1; break;
        default: src = w2; off = 8 * (size_t)M1; break;
    }
    const int i = blockIdx.x * 256 + threadIdx.x;
    float4 v = reinterpret_cast<const float4*>(src)[i];
    __half2* d = reinterpret_cast<__half2*>(dst + off) + i * 2;
    d[0] = __floats2half2_rn(v.x, v.y);
    d[1] = __floats2half2_rn(v.z, v.w);
}

__global__ void concat_bias_kernel(const float* __restrict__ bq, const float* __restrict__ bk,
                                   const float* __restrict__ bv, float* __restrict__ dst) {
    const int i = blockIdx.x * 256 + threadIdx.x;
    if (i < 1024) dst[i] = bq[i];
    else if (i < 2048) dst[i] = bk[i - 1024];
    else dst[i] = bv[i - 2048];
}

// ---------------------------------------------------------------------------
// LayerNorm (exact fp32 math): unbiased std (ddof=1), scalar alpha/beta.
// Output fp16 (feeds GEMM operands).
// ---------------------------------------------------------------------------
__global__ void layernorm_kernel(const float* __restrict__ x, __half* __restrict__ y,
                                 const float* __restrict__ alpha,
                                 const float* __restrict__ beta) {
    __shared__ float red_s[256];
    __shared__ float red_q[256];
    const int tid = threadIdx.x;
    const size_t off = (size_t)blockIdx.x * D_;
    float4 r = reinterpret_cast<const float4*>(x + off)[tid];
    float s = r.x + r.y + r.z + r.w;
    float q = r.x * r.x + r.y * r.y + r.z * r.z + r.w * r.w;
    red_s[tid] = s;
    red_q[tid] = q;
    __syncthreads();
    #pragma unroll
    for (int st = 128; st > 0; st >>= 1) {
        if (tid < st) { red_s[tid] += red_s[tid + st]; red_q[tid] += red_q[tid + st]; }
        __syncthreads();
    }
    const float mean = red_s[0] * (1.0f / D_);
    float var = (red_q[0] - (float)D_ * mean * mean) * (1.0f / (float)(D_ - 1));
    var = fmaxf(var, 0.0f);
    const float sc = alpha[0] / (sqrtf(var) + EPS_);
    const float sh = beta[0];
    __half2* yo = reinterpret_cast<__half2*>(y + off) + tid * 2;
    yo[0] = __floats2half2_rn((r.x - mean) * sc + sh, (r.y - mean) * sc + sh);
    yo[1] = __floats2half2_rn((r.z - mean) * sc + sh, (r.w - mean) * sc + sh);
}

// ---------------------------------------------------------------------------
// V transpose: vT[(b*H+h)][n][s] = qkv[b][s][2048 + h*DK + n]  (half)
// ---------------------------------------------------------------------------
__global__ void transpose_v_kernel(const __half* __restrict__ v, __half* __restrict__ vT) {
    __shared__ __half t[32][34];
    const int bh = blockIdx.z;
    const int b = bh / H_, h = bh % H_;
    const int s0 = blockIdx.x * 32, n0 = blockIdx.y * 32;
    const int tx = threadIdx.x, ty = threadIdx.y;   // 32 x 8
    const __half* src = v + ((long long)b * S_ + s0) * QKV_LD + h * DK_ + n0;
    #pragma unroll
    for (int i = 0; i < 32; i += 8)
        t[ty + i][tx] = src[(long long)(ty + i) * QKV_LD + tx];
    __syncthreads();
    __half* dst = vT + ((long long)bh * DK_ + n0) * S_ + s0;
    #pragma unroll
    for (int i = 0; i < 32; i += 8)
        dst[(long long)(ty + i) * S_ + tx] = t[tx][ty + i];
}

// ---------------------------------------------------------------------------
// fp16 tensor-core GEMM (NT): C = scale*A@B^T (+bias)(+relu)(+res).
// Block 128x128x64(half); warp tile 64x32; 8 warps; 3-stage cp.async pipeline.
// Rows are 128B (64 halfs) with XOR-16B-chunk swizzle -> same proven geometry.
// ---------------------------------------------------------------------------
template <bool RELU, bool OUTHALF>
__global__ void __launch_bounds__(256, 2)
mma_gemm(const __half* __restrict__ A, const __half* __restrict__ Bm,
         const float* __restrict__ bias, const float* __restrict__ res,
         void* __restrict__ Cv,
         int K, int lda, int ldb, int ldc, float scale) {
    constexpr int STGB = 256 * 128;   // bytes per stage
    constexpr int BOFFB = 128 * 128;  // B region offset (bytes)

    extern __shared__ char smc[];

    const int tid = threadIdx.x;
    const int wid = tid >> 5;
    const int lane = tid & 31;
    const int grp = lane >> 2;
    const int tid4 = lane & 3;
    const int wm0 = (wid >> 2) * 64;
    const int wn0 = (wid & 3) * 32;

    const int l7 = lane & 7;
    const int aRB = ((lane >> 3) & 1) * 8 + l7;
    const int aCB = lane >> 4;
    const int bRB = ((lane >> 4) & 1) * 8 + l7;
    const int bCB = (lane >> 3) & 1;

    const int row0 = blockIdx.y * 128;
    const int col0 = blockIdx.x * 128;

    int aGo[4]; uint32_t aSm[4];
    #pragma unroll
    for (int l = 0; l < 4; l++) {
        const int idx4 = tid + l * 256;
        const int r = idx4 >> 3, ch = idx4 & 7;
        aGo[l] = (row0 + r) * lda + ch * 8;
        aSm[l] = (uint32_t)(r * 128 + ((ch ^ (r & 7)) << 4));
    }
    int bGo[4]; uint32_t bSm[4];
    #pragma unroll
    for (int l = 0; l < 4; l++) {
        const int idx4 = tid + l * 256;
        const int r = idx4 >> 3, ch = idx4 & 7;
        bGo[l] = (col0 + r) * ldb + ch * 8;
        bSm[l] = (uint32_t)(BOFFB + r * 128 + ((ch ^ (r & 7)) << 4));
    }
    const uint32_t smBase = smem_u32(smc);

    float acc[4][4][4];
    #pragma unroll
    for (int i = 0; i < 4; i++)
        #pragma unroll
        for (int j = 0; j < 4; j++)
            #pragma unroll
            for (int e = 0; e < 4; e++) acc[i][j][e] = 0.0f;

    const int nch = K / 64;

    #pragma unroll
    for (int s = 0; s < 2; s++) {
        const uint32_t sb = smBase + (uint32_t)(s % 3) * STGB;
        const int k0 = s * 64;
        #pragma unroll
        for (int l = 0; l < 4; l++) cp_async16(sb + aSm[l], A + aGo[l] + k0);
        #pragma unroll
        for (int l = 0; l < 4; l++) cp_async16(sb + bSm[l], Bm + bGo[l] + k0);
        CP_COMMIT();
    }

    for (int ci = 0; ci < nch; ci++) {
        if (ci + 2 < nch) { CP_WAIT(1); } else { CP_WAIT(0); }
        __syncthreads();
        if (ci + 2 < nch) {
            const int s = ci + 2;
            const uint32_t sb = smBase + (uint32_t)(s % 3) * STGB;
            const int k0 = s * 64;
            #pragma unroll
            for (int l = 0; l < 4; l++) cp_async16(sb + aSm[l], A + aGo[l] + k0);
            #pragma unroll
            for (int l = 0; l < 4; l++) cp_async16(sb + bSm[l], Bm + bGo[l] + k0);
            CP_COMMIT();
        }

        const uint32_t suA = smBase + (uint32_t)(ci % 3) * STGB;
        const uint32_t suB = suA + (uint32_t)BOFFB;

        #pragma unroll
        for (int ks = 0; ks < 4; ks++) {
            const uint32_t aSw = (uint32_t)(((2 * ks + aCB) ^ l7) << 4);
            const uint32_t bSw = (uint32_t)(((2 * ks + bCB) ^ l7) << 4);
            uint32_t a[4][4];
            #pragma unroll
            for (int ma = 0; ma < 4; ma++)
                ldsm_x4(a[ma], suA + (uint32_t)(wm0 + ma * 16 + aRB) * 128u + aSw);
            uint32_t bq[2][4];
            #pragma unroll
            for (int np = 0; np < 2; np++)
                ldsm_x4(bq[np], suB + (uint32_t)(wn0 + np * 16 + bRB) * 128u + bSw);
            #pragma unroll
            for (int ma = 0; ma < 4; ma++)
                #pragma unroll
                for (int na = 0; na < 4; na++)
                    mma_f16(acc[ma][na], a[ma], &bq[na >> 1][(na & 1) * 2]);
        }
    }

    #pragma unroll
    for (int ma = 0; ma < 4; ma++) {
        const int rr = row0 + wm0 + ma * 16 + grp;
        #pragma unroll
        for (int na = 0; na < 4; na++) {
            const int cc = col0 + wn0 + na * 8 + tid4 * 2;
            float2 v0, v1;
            v0.x = acc[ma][na][0] * scale; v0.y = acc[ma][na][1] * scale;
            v1.x = acc[ma][na][2] * scale; v1.y = acc[ma][na][3] * scale;
            if (bias) {
                const float2 bv = *reinterpret_cast<const float2*>(bias + cc);
                v0.x += bv.x; v0.y += bv.y; v1.x += bv.x; v1.y += bv.y;
            }
            if (RELU) {
                v0.x = fmaxf(v0.x, 0.0f); v0.y = fmaxf(v0.y, 0.0f);
                v1.x = fmaxf(v1.x, 0.0f); v1.y = fmaxf(v1.y, 0.0f);
            }
            const long long o0 = (long long)rr * ldc + cc;
            const long long o1 = (long long)(rr + 8) * ldc + cc;
            if (OUTHALF) {
                __half* C = reinterpret_cast<__half*>(Cv);
                *reinterpret_cast<__half2*>(C + o0) = __floats2half2_rn(v0.x, v0.y);
                *reinterpret_cast<__half2*>(C + o1) = __floats2half2_rn(v1.x, v1.y);
            } else {
                float* C = reinterpret_cast<float*>(Cv);
                if (res) {
                    const float2 r0 = *reinterpret_cast<const float2*>(res + o0);
                    const float2 r1 = *reinterpret_cast<const float2*>(res + o1);
                    v0.x += r0.x; v0.y += r0.y; v1.x += r1.x; v1.y += r1.y;
                }
                *reinterpret_cast<float2*>(C + o0) = v0;
                *reinterpret_cast<float2*>(C + o1) = v1;
            }
        }
    }
}

// ---------------------------------------------------------------------------
// Fused flash attention (fp16 operands, fp32 softmax/accumulate).
// Per block: 64 q-rows, 128-kv tiles, 16 iterations; 2 CTAs/SM.
// Byte offsets: Q 64x128B=8K, K 128x128B=16K, VT 64x256B=16K, P 64x256B=16K,
//               red 512B.  Total 57856 B.
// ---------------------------------------------------------------------------
namespace fa {
constexpr int oQ = 0, oK = 8192, oVT = 24576, oP = 40960, oRed = 57344;
constexpr int SMEM_BYTES = 57856;
constexpr int NIT = S_ / 128;                  // 16
}

__global__ void __launch_bounds__(256, 2)
flash_attn_kernel(const __half* __restrict__ q, const __half* __restrict__ k,
                  const __half* __restrict__ vT, const int* __restrict__ mask,
                  __half* __restrict__ attn) {
    using namespace fa;
    extern __shared__ char smc[];
    float* smf = reinterpret_cast<float*>(smc);
    const uint32_t smb = smem_u32(smc);

    const int tid = threadIdx.x, wid = tid >> 5, lane = tid & 31;
    const int grp = lane >> 2, tid4 = lane & 3;
    const int wmS = (wid >> 1) * 16;    // rows owned (both phases)
    const int cw = wid & 1;
    const int wnS = cw * 64;            // S cols (K rows)
    const int wnB = cw * 32;            // PV dk cols

    const int l7 = lane & 7;
    const int aRB = ((lane >> 3) & 1) * 8 + l7;
    const int aCB = lane >> 4;
    const int bRB = ((lane >> 4) & 1) * 8 + l7;
    const int bCB = (lane >> 3) & 1;

    const int qt = blockIdx.x;
    const int bh = blockIdx.y;
    const int b = bh >> 4, hh = bh & 15;
    const int q0 = qt * 64;
    const __half* Qg = q + ((size_t)(b * S_ + q0)) * QKV_LD + hh * 64;
    const __half* Kg = k + ((size_t)(b * S_)) * QKV_LD + hh * 64;
    const __half* Vg = vT + (size_t)bh * 64 * S_;
    const int* maskb = mask + b * S_;

    // prologue: group0 = {Q, K0}, group1 = {VT0}
    #pragma unroll
    for (int l = 0; l < 2; l++) {
        const int i4 = tid + l * 256;
        const int r = i4 >> 3, c = i4 & 7;
        cp_async16(smb + (uint32_t)(oQ + r * 128 + ((c ^ (r & 7)) << 4)),
                   Qg + (size_t)r * QKV_LD + c * 8);
    }
    #pragma unroll
    for (int l = 0; l < 4; l++) {
        const int i4 = tid + l * 256;
        const int r = i4 >> 3, c = i4 & 7;
        cp_async16(smb + (uint32_t)(oK + r * 128 + ((c ^ (r & 7)) << 4)),
                   Kg + (size_t)r * QKV_LD + c * 8);
    }
    CP_COMMIT();
    #pragma unroll
    for (int l = 0; l < 4; l++) {
        const int i4 = tid + l * 256;
        const int r = i4 >> 4, c = i4 & 15;
        cp_async16(smb + (uint32_t)(oVT + r * 256 + ((c ^ (r & 7)) << 4)),
                   Vg + (size_t)r * S_ + c * 8);
    }
    CP_COMMIT();

    float acc_o[4][4];
    #pragma unroll
    for (int j = 0; j < 4; j++)
        #pragma unroll
        for (int e = 0; e < 4; e++) acc_o[j][e] = 0.0f;

    float m0 = -3.0e38f, m1 = -3.0e38f;
    float l0 = 0.0f, l1 = 0.0f;

    const int rA = wmS + grp;
    const int fRed = oRed / 4;
    const int red0 = fRed + rA * 2;
    const int red1 = fRed + (rA + 8) * 2;

    for (int it = 0; it < NIT; ++it) {
        const int kv0 = it * 128;
        CP_WAIT(1);                 // K(it) (and Q on it==0) ready
        __syncthreads();

        // ---- S = Q K^T (M=64, N=128, K=64 halfs = 4 ksteps) ----
        float acc_s[8][4];
        #pragma unroll
        for (int j = 0; j < 8; j++)
            #pragma unroll
            for (int e = 0; e < 4; e++) acc_s[j][e] = 0.0f;

        #pragma unroll
        for (int ks = 0; ks < 4; ks++) {
            const uint32_t aSw = (uint32_t)(((2 * ks + aCB) ^ l7) << 4);
            const uint32_t bSw = (uint32_t)(((2 * ks + bCB) ^ l7) << 4);
            uint32_t a[4];
            ldsm_x4(a, smb + (uint32_t)(oQ + (wmS + aRB) * 128) + aSw);
            uint32_t bq[4][4];
            #pragma unroll
            for (int np = 0; np < 4; np++)
                ldsm_x4(bq[np], smb + (uint32_t)(oK + (wnS + np * 16 + bRB) * 128) + bSw);
            #pragma unroll
            for (int na = 0; na < 8; na++)
                mma_f16(acc_s[na], a, &bq[na >> 1][(na & 1) * 2]);
        }
        __syncthreads();            // all K reads complete

        if (it + 1 < NIT) {         // reload K (overlaps softmax+PV)
            const __half* Kn = Kg + (size_t)(kv0 + 128) * QKV_LD;
            #pragma unroll
            for (int l = 0; l < 4; l++) {
                const int i4 = tid + l * 256;
                const int r = i4 >> 3, c = i4 & 7;
                cp_async16(smb + (uint32_t)(oK + r * 128 + ((c ^ (r & 7)) << 4)),
                           Kn + (size_t)r * QKV_LD + c * 8);
            }
            CP_COMMIT();
        }

        // ---- mask + scale + row max ----
        float p0 = -3.0e38f, p1 = -3.0e38f;
        #pragma unroll
        for (int na = 0; na < 8; na++) {
            const int cg = kv0 + wnS + na * 8 + tid4 * 2;
            const int2 mm = *reinterpret_cast<const int2*>(maskb + cg);
            float* s = acc_s[na];
            s[0] = mm.x ? s[0] * 0.125f : -1e9f;
            s[1] = mm.y ? s[1] * 0.125f : -1e9f;
            s[2] = mm.x ? s[2] * 0.125f : -1e9f;
            s[3] = mm.y ? s[3] * 0.125f : -1e9f;
            p0 = fmaxf(p0, fmaxf(s[0], s[1]));
            p1 = fmaxf(p1, fmaxf(s[2], s[3]));
        }
        #pragma unroll
        for (int d2 = 1; d2 < 4; d2 <<= 1) {
            p0 = fmaxf(p0, __shfl_xor_sync(0xffffffffu, p0, d2));
            p1 = fmaxf(p1, __shfl_xor_sync(0xffffffffu, p1, d2));
        }
        if (tid4 == 0) { smf[red0 + cw] = p0; smf[red1 + cw] = p1; }
        __syncthreads();
        const float mn0 = fmaxf(m0, fmaxf(smf[red0], smf[red0 + 1]));
        const float mn1 = fmaxf(m1, fmaxf(smf[red1], smf[red1 + 1]));
        const float c0 = __expf(m0 - mn0);
        const float c1 = __expf(m1 - mn1);
        m0 = mn0; m1 = mn1;
        __syncthreads();            // red reuse guard

        // ---- exp, P write (half), row sum ----
        float s0sum = 0.0f, s1sum = 0.0f;
        #pragma unroll
        for (int na = 0; na < 8; na++) {
            float* s = acc_s[na];
            s[0] = __expf(s[0] - mn0);
            s[1] = __expf(s[1] - mn0);
            s[2] = __expf(s[2] - mn1);
            s[3] = __expf(s[3] - mn1);
            s0sum += s[0] + s[1];
            s1sum += s[2] + s[3];
            // P row = 256B = 16 chunks; col pair at (cw*64 + na*8 + tid4*2) halfs
            const int ch = cw * 8 + na;                  // 16B chunk (8 halfs)
            const int sub = tid4 * 4;                    // byte offset in chunk
            const uint32_t bo = (uint32_t)(oP + rA * 256 + ((ch ^ grp) << 4) + sub);
            *reinterpret_cast<__half2*>(smc + bo) = __floats2half2_rn(s[0], s[1]);
            *reinterpret_cast<__half2*>(smc + bo + 2048) = __floats2half2_rn(s[2], s[3]);
        }
        #pragma unroll
        for (int d2 = 1; d2 < 4; d2 <<= 1) {
            s0sum += __shfl_xor_sync(0xffffffffu, s0sum, d2);
            s1sum += __shfl_xor_sync(0xffffffffu, s1sum, d2);
        }
        if (tid4 == 0) { smf[red0 + cw] = s0sum; smf[red1 + cw] = s1sum; }

        if (it + 1 < NIT) { CP_WAIT(1); } else { CP_WAIT(0); }   // VT(it) ready
        __syncthreads();            // P + psum + VT visible

        l0 = l0 * c0 + (smf[red0] + smf[red0 + 1]);
        l1 = l1 * c1 + (smf[red1] + smf[red1 + 1]);
        #pragma unroll
        for (int na = 0; na < 4; na++) {
            acc_o[na][0] *= c0; acc_o[na][1] *= c0;
            acc_o[na][2] *= c1; acc_o[na][3] *= c1;
        }

        // ---- PV: O += P @ VT^T (M=64, N=64, K=128 halfs = 8 ksteps) ----
        #pragma unroll
        for (int ks = 0; ks < 8; ks++) {
            const uint32_t aSw = (uint32_t)(((2 * ks + aCB) ^ l7) << 4);
            const uint32_t bSw = (uint32_t)(((2 * ks + bCB) ^ l7) << 4);
            uint32_t a[4];
            ldsm_x4(a, smb + (uint32_t)(oP + (wmS + aRB) * 256) + aSw);
            uint32_t bq[2][4];
            #pragma unroll
            for (int np = 0; np < 2; np++)
                ldsm_x4(bq[np], smb + (uint32_t)(oVT + (wnB + np * 16 + bRB) * 256) + bSw);
            #pragma unroll
            for (int na = 0; na < 4; na++)
                mma_f16(acc_o[na], a, &bq[na >> 1][(na & 1) * 2]);
        }
        __syncthreads();            // VT + P reads complete

        if (it + 1 < NIT) {         // reload VT (overlaps next S-MMA)
            const __half* Vn = Vg + kv0 + 128;
            #pragma unroll
            for (int l = 0; l < 4; l++) {
                const int i4 = tid + l * 256;
                const int r = i4 >> 4, c = i4 & 15;
                cp_async16(smb + (uint32_t)(oVT + r * 256 + ((c ^ (r & 7)) << 4)),
                           Vn + (size_t)r * S_ + c * 8);
            }
            CP_COMMIT();
        }
    }

    // ---- normalize and store (half; feeds Wo GEMM) ----
    const float inv0 = 1.0f / l0;
    const float inv1 = 1.0f / l1;
    #pragma unroll
    for (int na = 0; na < 4; na++) {
        const int cd = wnB + na * 8 + tid4 * 2;
        const size_t o0 = ((size_t)(b * S_ + q0 + rA)) * D_ + hh * 64 + cd;
        const size_t o1 = o0 + (size_t)8 * D_;
        *reinterpret_cast<__half2*>(attn + o0) =
            __floats2half2_rn(acc_o[na][0] * inv0, acc_o[na][1] * inv0);
        *reinterpret_cast<__half2*>(attn + o1) =
            __floats2half2_rn(acc_o[na][2] * inv1, acc_o[na][3] * inv1);
    }
}

// ---------------------------------------------------------------------------
// kernel_launch
// ---------------------------------------------------------------------------
extern "C" void kernel_launch(void* const* d_in, const int* in_sizes, int n_in,
                              void* d_out, int out_size) {
    const float* x    = (const float*)d_in[0];
    const int*   msk  = (const int*)  d_in[1];
    const float* wq   = (const float*)d_in[2];
    const float* bq   = (const float*)d_in[3];
    const float* wk   = (const float*)d_in[4];
    const float* bk_  = (const float*)d_in[5];
    const float* wv   = (const float*)d_in[6];
    const float* bv   = (const float*)d_in[7];
    const float* wo   = (const float*)d_in[8];
    const float* bo   = (const float*)d_in[9];
    const float* w1   = (const float*)d_in[10];
    const float* b1   = (const float*)d_in[11];
    const float* w2   = (const float*)d_in[12];
    const float* b2   = (const float*)d_in[13];
    const float* a1   = (const float*)d_in[14];
    const float* be1  = (const float*)d_in[15];
    const float* a2   = (const float*)d_in[16];
    const float* be2  = (const float*)d_in[17];
    float* out = (float*)d_out;

    __half *ln, *qkv, *vT, *attn, *hb, *wr;
    float *x2, *bqkv;
    cudaGetSymbolAddress((void**)&ln,   g_ln);
    cudaGetSymbolAddress((void**)&qkv,  g_qkv);
    cudaGetSymbolAddress((void**)&vT,   g_vT);
    cudaGetSymbolAddress((void**)&attn, g_attn);
    cudaGetSymbolAddress((void**)&x2,   g_x2);
    cudaGetSymbolAddress((void**)&hb,   g_hbuf);
    cudaGetSymbolAddress((void**)&wr,   g_wr);
    cudaGetSymbolAddress((void**)&bqkv, g_bqkv);

    constexpr int M1 = 1024 * 1024;
    __half* wqkvr = wr;            // [3072, 1024] (wq|wk|wv)
    __half* wor = wr + 3 * M1;
    __half* w1r = wr + 4 * M1;
    __half* w2r = wr + 8 * M1;

    constexpr int SMG = 3 * 256 * 128;   // 98304 bytes (3 stages)
    cudaFuncSetAttribute(mma_gemm<false, false>, cudaFuncAttributeMaxDynamicSharedMemorySize, SMG);
    cudaFuncSetAttribute(mma_gemm<false, true>,  cudaFuncAttributeMaxDynamicSharedMemorySize, SMG);
    cudaFuncSetAttribute(mma_gemm<true,  true>,  cudaFuncAttributeMaxDynamicSharedMemorySize, SMG);
    cudaFuncSetAttribute(flash_attn_kernel, cudaFuncAttributeMaxDynamicSharedMemorySize,
                         fa::SMEM_BYTES);

    // 0. weight conversion + bias concat
    round_all_kernel<<<dim3(4096, 6), 256>>>(wq, wk, wv, wo, w1, w2, wr);
    concat_bias_kernel<<<12, 256>>>(bq, bk_, bv, bqkv);

    // 1. LN1 (half output)
    layernorm_kernel<<<ROWS_, 256>>>(x, ln, a1, be1);

    // 2. fused QKV projection: [4096, 3072] (half out)
    mma_gemm<false, true><<<dim3(QKV_LD / 128, ROWS_ / 128), 256, SMG>>>(
        ln, wqkvr, bqkv, nullptr, qkv, D_, D_, D_, QKV_LD, 1.0f);

    // 3. vT from qkv's V columns
    transpose_v_kernel<<<dim3(S_ / 32, DK_ / 32, B_ * H_), dim3(32, 8)>>>(
        qkv + 2 * D_, vT);

    // 4. fused flash attention -> attn (half)
    flash_attn_kernel<<<dim3(S_ / 64, B_ * H_), 256, fa::SMEM_BYTES>>>(
        qkv, qkv + D_, vT, msk, attn);

    // 5. x2 = attn @ wo^T + bo + x (fp32 out + residual)
    mma_gemm<false, false><<<dim3(D_ / 128, ROWS_ / 128), 256, SMG>>>(
        attn, wor, bo, x, x2, D_, D_, D_, D_, 1.0f);

    // 6. LN2 (half output)
    layernorm_kernel<<<ROWS_, 256>>>(x2, ln, a2, be2);

    // 7. h = relu(ln @ w1^T + b1) (half out)
    mma_gemm<true, true><<<dim3(DFF_ / 128, ROWS_ / 128), 256, SMG>>>(
        ln, w1r, b1, nullptr, hb, D_, D_, D_, DFF_, 1.0f);

    // 8. out = h @ w2^T + b2 + x2 (fp32 out + residual)
    mma_gemm<false, false><<<dim3(D_ / 128, ROWS_ / 128), 256, SMG>>>(
        hb, w2r, b2, x2, out, DFF_, DFF_, DFF_, D_, 1.0f);
}

// round 10
// speedup vs baseline: 1.7578x; 1.0042x over previous
#include <cuda_runtime.h>
#include <cuda_fp16.h>
#include <cstdint>

// ---------------------------------------------------------------------------
// EncoderBlock: pre-norm transformer block.
// GEMMs + flash attention via mma.sync m16n8k16 fp16 (fp32 accumulate).
// FA: double-buffered K/VT, 3 barriers per kv-iteration.
// B=2, S=2048, D=1024, H=16, DK=64, DFF=4096
// ---------------------------------------------------------------------------

namespace {
constexpr int B_ = 2, S_ = 2048, D_ = 1024, H_ = 16, DK_ = 64, DFF_ = 4096;
constexpr int ROWS_ = B_ * S_;            // 4096
constexpr int QKV_LD = 3 * D_;            // 3072
constexpr float EPS_ = 1e-6f;
}

// Scratch (allocation-free: __device__ globals)
__device__ __align__(16) __half g_ln[ROWS_ * D_];
__device__ __align__(16) __half g_qkv[ROWS_ * QKV_LD];
__device__ __align__(16) __half g_vT[B_ * H_ * DK_ * S_];
__device__ __align__(16) __half g_attn[ROWS_ * D_];
__device__ __align__(16) float  g_x2[ROWS_ * D_];
__device__ __align__(16) __half g_hbuf[ROWS_ * DFF_];
__device__ __align__(16) __half g_wr[12 * 1024 * 1024];   // half weights (24MB)
__device__ __align__(16) float  g_bqkv[QKV_LD];

// ---------------------------------------------------------------------------
// PTX helpers
// ---------------------------------------------------------------------------
__device__ __forceinline__ uint32_t smem_u32(const void* p) {
    uint32_t a;
    asm("{ .reg .u64 t; cvta.to.shared.u64 t, %1; cvt.u32.u64 %0, t; }"
        : "=r"(a) : "l"(p));
    return a;
}

__device__ __forceinline__ void cp_async16(uint32_t s, const void* g) {
    asm volatile("cp.async.cg.shared.global [%0], [%1], 16;" :: "r"(s), "l"(g));
}
#define CP_COMMIT() asm volatile("cp.async.commit_group;" ::: "memory")
#define CP_WAIT(n)  asm volatile("cp.async.wait_group %0;" :: "n"(n) : "memory")

__device__ __forceinline__ void mma_f16(float* c, const uint32_t* a, const uint32_t* b) {
    asm volatile(
        "mma.sync.aligned.m16n8k16.row.col.f32.f16.f16.f32 "
        "{%0,%1,%2,%3}, {%4,%5,%6,%7}, {%8,%9}, {%0,%1,%2,%3};"
        : "+f"(c[0]), "+f"(c[1]), "+f"(c[2]), "+f"(c[3])
        : "r"(a[0]), "r"(a[1]), "r"(a[2]), "r"(a[3]), "r"(b[0]), "r"(b[1]));
}

__device__ __forceinline__ void ldsm_x4(uint32_t* r, uint32_t saddr) {
    asm volatile("ldmatrix.sync.aligned.m8n8.x4.shared.b16 {%0,%1,%2,%3}, [%4];"
                 : "=r"(r[0]), "=r"(r[1]), "=r"(r[2]), "=r"(r[3]) : "r"(saddr));
}

// ---------------------------------------------------------------------------
// Weight conversion fp32 -> fp16 + bias concat (one launch).
// dst: [wq 1M][wk 1M][wv 1M][wo 1M][w1 4M][w2 4M] halfs
// ---------------------------------------------------------------------------
__global__ void round_all_kernel(const float* __restrict__ wq, const float* __restrict__ wk,
                                 const float* __restrict__ wv, const float* __restrict__ wo,
                                 const float* __restrict__ w1, const float* __restrict__ w2,
                                 const float* __restrict__ bq, const float* __restrict__ bk,
                                 const float* __restrict__ bv,
                                 __half* __restrict__ dst, float* __restrict__ bqkv) {
    constexpr int M1 = 1024 * 1024;
    const int y = blockIdx.y;
    if (y == 6) {   // bias concat: 3072 floats
        if (blockIdx.x >= 12) return;
        const int i = blockIdx.x * 256 + threadIdx.x;
        if (i < 1024) bqkv[i] = bq[i];
        else if (i < 2048) bqkv[i] = bk[i - 1024];
        else bqkv[i] = bv[i - 2048];
        return;
    }
    if (y < 4 && blockIdx.x >= 1024) return;
    const float* src;
    size_t off;
    switch (y) {
        case 0: src = wq; off = 0; break;
        case 1: src = wk; off = (size_t)M1; break;
        case 2: src = wv; off = 2 * (size_t)M1; break;
        case 3: src = wo; off = 3 * (size_t)M1; break;
        case 4: src = w1; off = 4 * (size_t)M1; break;
        default: src = w2; off = 8 * (size_t)M1; break;
    }
    const int i = blockIdx.x * 256 + threadIdx.x;
    float4 v = reinterpret_cast<const float4*>(src)[i];
    __half2* d = reinterpret_cast<__half2*>(dst + off) + i * 2;
    d[0] = __floats2half2_rn(v.x, v.y);
    d[1] = __floats2half2_rn(v.z, v.w);
}

// ---------------------------------------------------------------------------
// LayerNorm (exact fp32 math): unbiased std (ddof=1), scalar alpha/beta.
// ---------------------------------------------------------------------------
__global__ void layernorm_kernel(const float* __restrict__ x, __half* __restrict__ y,
                                 const float* __restrict__ alpha,
                                 const float* __restrict__ beta) {
    __shared__ float red_s[256];
    __shared__ float red_q[256];
    const int tid = threadIdx.x;
    const size_t off = (size_t)blockIdx.x * D_;
    float4 r = reinterpret_cast<const float4*>(x + off)[tid];
    float s = r.x + r.y + r.z + r.w;
    float q = r.x * r.x + r.y * r.y + r.z * r.z + r.w * r.w;
    red_s[tid] = s;
    red_q[tid] = q;
    __syncthreads();
    #pragma unroll
    for (int st = 128; st > 0; st >>= 1) {
        if (tid < st) { red_s[tid] += red_s[tid + st]; red_q[tid] += red_q[tid + st]; }
        __syncthreads();
    }
    const float mean = red_s[0] * (1.0f / D_);
    float var = (red_q[0] - (float)D_ * mean * mean) * (1.0f / (float)(D_ - 1));
    var = fmaxf(var, 0.0f);
    const float sc = alpha[0] / (sqrtf(var) + EPS_);
    const float sh = beta[0];
    __half2* yo = reinterpret_cast<__half2*>(y + off) + tid * 2;
    yo[0] = __floats2half2_rn((r.x - mean) * sc + sh, (r.y - mean) * sc + sh);
    yo[1] = __floats2half2_rn((r.z - mean) * sc + sh, (r.w - mean) * sc + sh);
}

// ---------------------------------------------------------------------------
// V transpose: vT[(b*H+h)][n][s] = qkv[b][s][2048 + h*DK + n]  (half)
// ---------------------------------------------------------------------------
__global__ void transpose_v_kernel(const __half* __restrict__ v, __half* __restrict__ vT) {
    __shared__ __half t[32][34];
    const int bh = blockIdx.z;
    const int b = bh / H_, h = bh % H_;
    const int s0 = blockIdx.x * 32, n0 = blockIdx.y * 32;
    const int tx = threadIdx.x, ty = threadIdx.y;   // 32 x 8
    const __half* src = v + ((long long)b * S_ + s0) * QKV_LD + h * DK_ + n0;
    #pragma unroll
    for (int i = 0; i < 32; i += 8)
        t[ty + i][tx] = src[(long long)(ty + i) * QKV_LD + tx];
    __syncthreads();
    __half* dst = vT + ((long long)bh * DK_ + n0) * S_ + s0;
    #pragma unroll
    for (int i = 0; i < 32; i += 8)
        dst[(long long)(ty + i) * S_ + tx] = t[tx][ty + i];
}

// ---------------------------------------------------------------------------
// fp16 tensor-core GEMM (NT): C = scale*A@B^T (+bias)(+relu)(+res).
// Block 128x128x64(half); warp tile 64x32; 8 warps; 3-stage cp.async pipeline.
// ---------------------------------------------------------------------------
template <bool RELU, bool OUTHALF>
__global__ void __launch_bounds__(256, 2)
mma_gemm(const __half* __restrict__ A, const __half* __restrict__ Bm,
         const float* __restrict__ bias, const float* __restrict__ res,
         void* __restrict__ Cv,
         int K, int lda, int ldb, int ldc, float scale) {
    constexpr int STGB = 256 * 128;   // bytes per stage
    constexpr int BOFFB = 128 * 128;  // B region offset (bytes)

    extern __shared__ char smc[];

    const int tid = threadIdx.x;
    const int wid = tid >> 5;
    const int lane = tid & 31;
    const int grp = lane >> 2;
    const int tid4 = lane & 3;
    const int wm0 = (wid >> 2) * 64;
    const int wn0 = (wid & 3) * 32;

    const int l7 = lane & 7;
    const int aRB = ((lane >> 3) & 1) * 8 + l7;
    const int aCB = lane >> 4;
    const int bRB = ((lane >> 4) & 1) * 8 + l7;
    const int bCB = (lane >> 3) & 1;

    const int row0 = blockIdx.y * 128;
    const int col0 = blockIdx.x * 128;

    int aGo[4]; uint32_t aSm[4];
    #pragma unroll
    for (int l = 0; l < 4; l++) {
        const int idx4 = tid + l * 256;
        const int r = idx4 >> 3, ch = idx4 & 7;
        aGo[l] = (row0 + r) * lda + ch * 8;
        aSm[l] = (uint32_t)(r * 128 + ((ch ^ (r & 7)) << 4));
    }
    int bGo[4]; uint32_t bSm[4];
    #pragma unroll
    for (int l = 0; l < 4; l++) {
        const int idx4 = tid + l * 256;
        const int r = idx4 >> 3, ch = idx4 & 7;
        bGo[l] = (col0 + r) * ldb + ch * 8;
        bSm[l] = (uint32_t)(BOFFB + r * 128 + ((ch ^ (r & 7)) << 4));
    }
    const uint32_t smBase = smem_u32(smc);

    float acc[4][4][4];
    #pragma unroll
    for (int i = 0; i < 4; i++)
        #pragma unroll
        for (int j = 0; j < 4; j++)
            #pragma unroll
            for (int e = 0; e < 4; e++) acc[i][j][e] = 0.0f;

    const int nch = K / 64;

    #pragma unroll
    for (int s = 0; s < 2; s++) {
        const uint32_t sb = smBase + (uint32_t)(s % 3) * STGB;
        const int k0 = s * 64;
        #pragma unroll
        for (int l = 0; l < 4; l++) cp_async16(sb + aSm[l], A + aGo[l] + k0);
        #pragma unroll
        for (int l = 0; l < 4; l++) cp_async16(sb + bSm[l], Bm + bGo[l] + k0);
        CP_COMMIT();
    }

    for (int ci = 0; ci < nch; ci++) {
        if (ci + 2 < nch) { CP_WAIT(1); } else { CP_WAIT(0); }
        __syncthreads();
        if (ci + 2 < nch) {
            const int s = ci + 2;
            const uint32_t sb = smBase + (uint32_t)(s % 3) * STGB;
            const int k0 = s * 64;
            #pragma unroll
            for (int l = 0; l < 4; l++) cp_async16(sb + aSm[l], A + aGo[l] + k0);
            #pragma unroll
            for (int l = 0; l < 4; l++) cp_async16(sb + bSm[l], Bm + bGo[l] + k0);
            CP_COMMIT();
        }

        const uint32_t suA = smBase + (uint32_t)(ci % 3) * STGB;
        const uint32_t suB = suA + (uint32_t)BOFFB;

        #pragma unroll
        for (int ks = 0; ks < 4; ks++) {
            const uint32_t aSw = (uint32_t)(((2 * ks + aCB) ^ l7) << 4);
            const uint32_t bSw = (uint32_t)(((2 * ks + bCB) ^ l7) << 4);
            uint32_t a[4][4];
            #pragma unroll
            for (int ma = 0; ma < 4; ma++)
                ldsm_x4(a[ma], suA + (uint32_t)(wm0 + ma * 16 + aRB) * 128u + aSw);
            uint32_t bq[2][4];
            #pragma unroll
            for (int np = 0; np < 2; np++)
                ldsm_x4(bq[np], suB + (uint32_t)(wn0 + np * 16 + bRB) * 128u + bSw);
            #pragma unroll
            for (int ma = 0; ma < 4; ma++)
                #pragma unroll
                for (int na = 0; na < 4; na++)
                    mma_f16(acc[ma][na], a[ma], &bq[na >> 1][(na & 1) * 2]);
        }
    }

    #pragma unroll
    for (int ma = 0; ma < 4; ma++) {
        const int rr = row0 + wm0 + ma * 16 + grp;
        #pragma unroll
        for (int na = 0; na < 4; na++) {
            const int cc = col0 + wn0 + na * 8 + tid4 * 2;
            float2 v0, v1;
            v0.x = acc[ma][na][0] * scale; v0.y = acc[ma][na][1] * scale;
            v1.x = acc[ma][na][2] * scale; v1.y = acc[ma][na][3] * scale;
            if (bias) {
                const float2 bv = *reinterpret_cast<const float2*>(bias + cc);
                v0.x += bv.x; v0.y += bv.y; v1.x += bv.x; v1.y += bv.y;
            }
            if (RELU) {
                v0.x = fmaxf(v0.x, 0.0f); v0.y = fmaxf(v0.y, 0.0f);
                v1.x = fmaxf(v1.x, 0.0f); v1.y = fmaxf(v1.y, 0.0f);
            }
            const long long o0 = (long long)rr * ldc + cc;
            const long long o1 = (long long)(rr + 8) * ldc + cc;
            if (OUTHALF) {
                __half* C = reinterpret_cast<__half*>(Cv);
                *reinterpret_cast<__half2*>(C + o0) = __floats2half2_rn(v0.x, v0.y);
                *reinterpret_cast<__half2*>(C + o1) = __floats2half2_rn(v1.x, v1.y);
            } else {
                float* C = reinterpret_cast<float*>(Cv);
                if (res) {
                    const float2 r0 = *reinterpret_cast<const float2*>(res + o0);
                    const float2 r1 = *reinterpret_cast<const float2*>(res + o1);
                    v0.x += r0.x; v0.y += r0.y; v1.x += r1.x; v1.y += r1.y;
                }
                *reinterpret_cast<float2*>(C + o0) = v0;
                *reinterpret_cast<float2*>(C + o1) = v1;
            }
        }
    }
}

// ---------------------------------------------------------------------------
// Fused flash attention (fp16 operands, fp32 softmax/accumulate).
// 64 q-rows/block, 128-kv tiles, double-buffered K/VT, 3 barriers/iter.
// Bytes: Q 8K | K 2x16K | VT 2x16K | P 16K | redM 512 | redS 512 = 91136 B.
// 2 CTAs/SM (182KB < 228KB).
// ---------------------------------------------------------------------------
namespace fa {
constexpr int oQ = 0, oK = 8192, oVT = 40960, oP = 73728;
constexpr int oRedM = 90112, oRedS = 90624;
constexpr int SMEM_BYTES = 91136;
constexpr int NIT = S_ / 128;                  // 16
}

__global__ void __launch_bounds__(256, 2)
flash_attn_kernel(const __half* __restrict__ q, const __half* __restrict__ k,
                  const __half* __restrict__ vT, const int* __restrict__ mask,
                  __half* __restrict__ attn) {
    using namespace fa;
    extern __shared__ char smc[];
    float* smf = reinterpret_cast<float*>(smc);
    const uint32_t smb = smem_u32(smc);

    const int tid = threadIdx.x, wid = tid >> 5, lane = tid & 31;
    const int grp = lane >> 2, tid4 = lane & 3;
    const int wmS = (wid >> 1) * 16;    // rows owned (both phases)
    const int cw = wid & 1;
    const int wnS = cw * 64;            // S cols (K rows)
    const int wnB = cw * 32;            // PV dk cols

    const int l7 = lane & 7;
    const int aRB = ((lane >> 3) & 1) * 8 + l7;
    const int aCB = lane >> 4;
    const int bRB = ((lane >> 4) & 1) * 8 + l7;
    const int bCB = (lane >> 3) & 1;

    const int qt = blockIdx.x;
    const int bh = blockIdx.y;
    const int b = bh >> 4, hh = bh & 15;
    const int q0 = qt * 64;
    const __half* Qg = q + ((size_t)(b * S_ + q0)) * QKV_LD + hh * 64;
    const __half* Kg = k + ((size_t)(b * S_)) * QKV_LD + hh * 64;
    const __half* Vg = vT + (size_t)bh * 64 * S_;
    const int* maskb = mask + b * S_;

    // prologue: G1 = {Q, K0 -> buf0}, G2 = {VT0 -> buf0}
    #pragma unroll
    for (int l = 0; l < 2; l++) {
        const int i4 = tid + l * 256;
        const int r = i4 >> 3, c = i4 & 7;
        cp_async16(smb + (uint32_t)(oQ + r * 128 + ((c ^ (r & 7)) << 4)),
                   Qg + (size_t)r * QKV_LD + c * 8);
    }
    #pragma unroll
    for (int l = 0; l < 4; l++) {
        const int i4 = tid + l * 256;
        const int r = i4 >> 3, c = i4 & 7;
        cp_async16(smb + (uint32_t)(oK + r * 128 + ((c ^ (r & 7)) << 4)),
                   Kg + (size_t)r * QKV_LD + c * 8);
    }
    CP_COMMIT();
    #pragma unroll
    for (int l = 0; l < 4; l++) {
        const int i4 = tid + l * 256;
        const int r = i4 >> 4, c = i4 & 15;
        cp_async16(smb + (uint32_t)(oVT + r * 256 + ((c ^ (r & 7)) << 4)),
                   Vg + (size_t)r * S_ + c * 8);
    }
    CP_COMMIT();

    float acc_o[4][4];
    #pragma unroll
    for (int j = 0; j < 4; j++)
        #pragma unroll
        for (int e = 0; e < 4; e++) acc_o[j][e] = 0.0f;

    float m0 = -3.0e38f, m1 = -3.0e38f;
    float l0 = 0.0f, l1 = 0.0f;

    const int rA = wmS + grp;
    const int fRedM = oRedM / 4, fRedS = oRedS / 4;
    const int rm0 = fRedM + rA * 2, rm1 = fRedM + (rA + 8) * 2;
    const int rs0 = fRedS + rA * 2, rs1 = fRedS + (rA + 8) * 2;

    for (int it = 0; it < NIT; ++it) {
        const int kv0 = it * 128;
        const uint32_t kCur = smb + (uint32_t)(oK + (it & 1) * 16384);
        const uint32_t vCur = smb + (uint32_t)(oVT + (it & 1) * 16384);

        CP_WAIT(1);                 // K(it) complete (leaves VT(it))
        __syncthreads();            // barrier A

        // issue K(it+1) into the other buffer (no hazard with S-MMA reads)
        if (it + 1 < NIT) {
            const uint32_t kNxt = smb + (uint32_t)(oK + ((it + 1) & 1) * 16384);
            const __half* Kn = Kg + (size_t)(kv0 + 128) * QKV_LD;
            #pragma unroll
            for (int l = 0; l < 4; l++) {
                const int i4 = tid + l * 256;
                const int r = i4 >> 3, c = i4 & 7;
                cp_async16(kNxt + (uint32_t)(r * 128 + ((c ^ (r & 7)) << 4)),
                           Kn + (size_t)r * QKV_LD + c * 8);
            }
            CP_COMMIT();            // pending: {VT(it), K(it+1)}
        }

        // ---- S = Q K^T (M=64, N=128, K=64 halfs = 4 ksteps) ----
        float acc_s[8][4];
        #pragma unroll
        for (int j = 0; j < 8; j++)
            #pragma unroll
            for (int e = 0; e < 4; e++) acc_s[j][e] = 0.0f;

        #pragma unroll
        for (int ks = 0; ks < 4; ks++) {
            const uint32_t aSw = (uint32_t)(((2 * ks + aCB) ^ l7) << 4);
            const uint32_t bSw = (uint32_t)(((2 * ks + bCB) ^ l7) << 4);
            uint32_t a[4];
            ldsm_x4(a, smb + (uint32_t)(oQ + (wmS + aRB) * 128) + aSw);
            uint32_t bq[4][4];
            #pragma unroll
            for (int np = 0; np < 4; np++)
                ldsm_x4(bq[np], kCur + (uint32_t)((wnS + np * 16 + bRB) * 128) + bSw);
            #pragma unroll
            for (int na = 0; na < 8; na++)
                mma_f16(acc_s[na], a, &bq[na >> 1][(na & 1) * 2]);
        }

        // ---- mask + scale + row max ----
        float p0 = -3.0e38f, p1 = -3.0e38f;
        #pragma unroll
        for (int na = 0; na < 8; na++) {
            const int cg = kv0 + wnS + na * 8 + tid4 * 2;
            const int2 mm = *reinterpret_cast<const int2*>(maskb + cg);
            float* s = acc_s[na];
            s[0] = mm.x ? s[0] * 0.125f : -1e9f;
            s[1] = mm.y ? s[1] * 0.125f : -1e9f;
            s[2] = mm.x ? s[2] * 0.125f : -1e9f;
            s[3] = mm.y ? s[3] * 0.125f : -1e9f;
            p0 = fmaxf(p0, fmaxf(s[0], s[1]));
            p1 = fmaxf(p1, fmaxf(s[2], s[3]));
        }
        #pragma unroll
        for (int d2 = 1; d2 < 4; d2 <<= 1) {
            p0 = fmaxf(p0, __shfl_xor_sync(0xffffffffu, p0, d2));
            p1 = fmaxf(p1, __shfl_xor_sync(0xffffffffu, p1, d2));
        }
        if (tid4 == 0) { smf[rm0 + cw] = p0; smf[rm1 + cw] = p1; }
        __syncthreads();            // barrier B
        const float mn0 = fmaxf(m0, fmaxf(smf[rm0], smf[rm0 + 1]));
        const float mn1 = fmaxf(m1, fmaxf(smf[rm1], smf[rm1 + 1]));
        const float c0 = __expf(m0 - mn0);
        const float c1 = __expf(m1 - mn1);
        m0 = mn0; m1 = mn1;

        // ---- exp, P write (half, warp-local rows), row sum ----
        float s0sum = 0.0f, s1sum = 0.0f;
        #pragma unroll
        for (int na = 0; na < 8; na++) {
            float* s = acc_s[na];
            s[0] = __expf(s[0] - mn0);
            s[1] = __expf(s[1] - mn0);
            s[2] = __expf(s[2] - mn1);
            s[3] = __expf(s[3] - mn1);
            s0sum += s[0] + s[1];
            s1sum += s[2] + s[3];
            const int ch = cw * 8 + na;                  // 16B chunk (8 halfs)
            const int sub = tid4 * 4;                    // byte offset in chunk
            const uint32_t bo = (uint32_t)(oP + rA * 256 + ((ch ^ grp) << 4) + sub);
            *reinterpret_cast<__half2*>(smc + bo) = __floats2half2_rn(s[0], s[1]);
            *reinterpret_cast<__half2*>(smc + bo + 2048) = __floats2half2_rn(s[2], s[3]);
        }
        #pragma unroll
        for (int d2 = 1; d2 < 4; d2 <<= 1) {
            s0sum += __shfl_xor_sync(0xffffffffu, s0sum, d2);
            s1sum += __shfl_xor_sync(0xffffffffu, s1sum, d2);
        }
        if (tid4 == 0) { smf[rs0 + cw] = s0sum; smf[rs1 + cw] = s1sum; }

        if (it + 1 < NIT) { CP_WAIT(1); } else { CP_WAIT(0); }   // VT(it) done

        // issue VT(it+1) into the other buffer
        if (it + 1 < NIT) {
            const uint32_t vNxt = smb + (uint32_t)(oVT + ((it + 1) & 1) * 16384);
            const __half* Vn = Vg + kv0 + 128;
            #pragma unroll
            for (int l = 0; l < 4; l++) {
                const int i4 = tid + l * 256;
                const int r = i4 >> 4, c = i4 & 15;
                cp_async16(vNxt + (uint32_t)(r * 256 + ((c ^ (r & 7)) << 4)),
                           Vn + (size_t)r * S_ + c * 8);
            }
            CP_COMMIT();            // pending: {K(it+1), VT(it+1)}
        }
        __syncthreads();            // barrier C: P + sums + VT(it) visible

        l0 = l0 * c0 + (smf[rs0] + smf[rs0 + 1]);
        l1 = l1 * c1 + (smf[rs1] + smf[rs1 + 1]);
        #pragma unroll
        for (int na = 0; na < 4; na++) {
            acc_o[na][0] *= c0; acc_o[na][1] *= c0;
            acc_o[na][2] *= c1; acc_o[na][3] *= c1;
        }

        // ---- PV: O += P @ VT^T (M=64, N=64, K=128 halfs = 8 ksteps) ----
        #pragma unroll
        for (int ks = 0; ks < 8; ks++) {
            const uint32_t aSw = (uint32_t)(((2 * ks + aCB) ^ l7) << 4);
            const uint32_t bSw = (uint32_t)(((2 * ks + bCB) ^ l7) << 4);
            uint32_t a[4];
            ldsm_x4(a, smb + (uint32_t)(oP + (wmS + aRB) * 256) + aSw);
            uint32_t bq[2][4];
            #pragma unroll
            for (int np = 0; np < 2; np++)
                ldsm_x4(bq[np], vCur + (uint32_t)((wnB + np * 16 + bRB) * 256) + bSw);
            #pragma unroll
            for (int na = 0; na < 4; na++)
                mma_f16(acc_o[na], a, &bq[na >> 1][(na & 1) * 2]);
        }
        // no trailing barrier: next iter's barrier A orders PV reads before
        // the next P/red writes; K/VT reloads target disjoint buffers.
    }

    // ---- normalize and store (half; feeds Wo GEMM) ----
    const float inv0 = 1.0f / l0;
    const float inv1 = 1.0f / l1;
    #pragma unroll
    for (int na = 0; na < 4; na++) {
        const int cd = wnB + na * 8 + tid4 * 2;
        const size_t o0 = ((size_t)(b * S_ + q0 + rA)) * D_ + hh * 64 + cd;
        const size_t o1 = o0 + (size_t)8 * D_;
        *reinterpret_cast<__half2*>(attn + o0) =
            __floats2half2_rn(acc_o[na][0] * inv0, acc_o[na][1] * inv0);
        *reinterpret_cast<__half2*>(attn + o1) =
            __floats2half2_rn(acc_o[na][2] * inv1, acc_o[na][3] * inv1);
    }
}

// ---------------------------------------------------------------------------
// kernel_launch
// ---------------------------------------------------------------------------
extern "C" void kernel_launch(void* const* d_in, const int* in_sizes, int n_in,
                              void* d_out, int out_size) {
    const float* x    = (const float*)d_in[0];
    const int*   msk  = (const int*)  d_in[1];
    const float* wq   = (const float*)d_in[2];
    const float* bq   = (const float*)d_in[3];
    const float* wk   = (const float*)d_in[4];
    const float* bk_  = (const float*)d_in[5];
    const float* wv   = (const float*)d_in[6];
    const float* bv   = (const float*)d_in[7];
    const float* wo   = (const float*)d_in[8];
    const float* bo   = (const float*)d_in[9];
    const float* w1   = (const float*)d_in[10];
    const float* b1   = (const float*)d_in[11];
    const float* w2   = (const float*)d_in[12];
    const float* b2   = (const float*)d_in[13];
    const float* a1   = (const float*)d_in[14];
    const float* be1  = (const float*)d_in[15];
    const float* a2   = (const float*)d_in[16];
    const float* be2  = (const float*)d_in[17];
    float* out = (float*)d_out;

    __half *ln, *qkv, *vT, *attn, *hb, *wr;
    float *x2, *bqkv;
    cudaGetSymbolAddress((void**)&ln,   g_ln);
    cudaGetSymbolAddress((void**)&qkv,  g_qkv);
    cudaGetSymbolAddress((void**)&vT,   g_vT);
    cudaGetSymbolAddress((void**)&attn, g_attn);
    cudaGetSymbolAddress((void**)&x2,   g_x2);
    cudaGetSymbolAddress((void**)&hb,   g_hbuf);
    cudaGetSymbolAddress((void**)&wr,   g_wr);
    cudaGetSymbolAddress((void**)&bqkv, g_bqkv);

    constexpr int M1 = 1024 * 1024;
    __half* wqkvr = wr;            // [3072, 1024] (wq|wk|wv)
    __half* wor = wr + 3 * M1;
    __half* w1r = wr + 4 * M1;
    __half* w2r = wr + 8 * M1;

    constexpr int SMG = 3 * 256 * 128;   // 98304 bytes (3 stages)
    cudaFuncSetAttribute(mma_gemm<false, false>, cudaFuncAttributeMaxDynamicSharedMemorySize, SMG);
    cudaFuncSetAttribute(mma_gemm<false, true>,  cudaFuncAttributeMaxDynamicSharedMemorySize, SMG);
    cudaFuncSetAttribute(mma_gemm<true,  true>,  cudaFuncAttributeMaxDynamicSharedMemorySize, SMG);
    cudaFuncSetAttribute(flash_attn_kernel, cudaFuncAttributeMaxDynamicSharedMemorySize,
                         fa::SMEM_BYTES);

    // 0. weight conversion + bias concat (single launch)
    round_all_kernel<<<dim3(4096, 7), 256>>>(wq, wk, wv, wo, w1, w2,
                                             bq, bk_, bv, wr, bqkv);

    // 1. LN1 (half output)
    layernorm_kernel<<<ROWS_, 256>>>(x, ln, a1, be1);

    // 2. fused QKV projection: [4096, 3072] (half out)
    mma_gemm<false, true><<<dim3(QKV_LD / 128, ROWS_ / 128), 256, SMG>>>(
        ln, wqkvr, bqkv, nullptr, qkv, D_, D_, D_, QKV_LD, 1.0f);

    // 3. vT from qkv's V columns
    transpose_v_kernel<<<dim3(S_ / 32, DK_ / 32, B_ * H_), dim3(32, 8)>>>(
        qkv + 2 * D_, vT);

    // 4. fused flash attention -> attn (half)
    flash_attn_kernel<<<dim3(S_ / 64, B_ * H_), 256, fa::SMEM_BYTES>>>(
        qkv, qkv + D_, vT, msk, attn);

    // 5. x2 = attn @ wo^T + bo + x (fp32 out + residual)
    mma_gemm<false, false><<<dim3(D_ / 128, ROWS_ / 128), 256, SMG>>>(
        attn, wor, bo, x, x2, D_, D_, D_, D_, 1.0f);

    // 6. LN2 (half output)
    layernorm_kernel<<<ROWS_, 256>>>(x2, ln, a2, be2);

    // 7. h = relu(ln @ w1^T + b1) (half out)
    mma_gemm<true, true><<<dim3(DFF_ / 128, ROWS_ / 128), 256, SMG>>>(
        ln, w1r, b1, nullptr, hb, D_, D_, D_, DFF_, 1.0f);

    // 8. out = h @ w2^T + b2 + x2 (fp32 out + residual)
    mma_gemm<false, false><<<dim3(D_ / 128, ROWS_ / 128), 256, SMG>>>(
        hb, w2r, b2, x2, out, DFF_, DFF_, DFF_, D_, 1.0f);
}